// round 2
// baseline (speedup 1.0000x reference)
#include <cuda_runtime.h>
#include <math.h>

// Problem constants
#define BB 2
#define DD 160
#define HH 160
#define WW 160
#define SLICE (HH*WW)          // 25600
#define VOL (DD*SLICE)         // 4096000
#define TOTAL (BB*VOL)         // 8192000
#define RAD 5
#define WIN 11
#define TH 32                  // h-rows per tile in kernel 1
#define HR (TH + 2*RAD)        // 42 rows incl halo
#define SXP 165                // padded smem row stride for x/y slabs (odd -> few bank conflicts)
#define SPP 161                // padded smem row stride for product sums (odd)
#define NBLK1 (5*DD*BB)        // 1600 blocks in kernel 1
#define NSPLIT 2
#define DR (DD/NSPLIT)         // 80 d-steps per thread in kernel 2
#define NCOLS (BB*SLICE)       // 51200 columns
#define NBLK2 ((NCOLS*NSPLIT)/256)  // 400 blocks in kernel 2

// Global scratch: 5 box-summed (W,H) fields + reduction partials.
__device__ float g_swh[5][TOTAL];
__device__ float g_l1p[NBLK1];
__device__ float g_ssimp[NBLK2];

// ---------------------------------------------------------------------------
// Kernel 1: per (b,d,h-tile): products + sliding W-sum + sliding H-sum.
// Also accumulates smooth-L1 partial over owned rows.
// ---------------------------------------------------------------------------
__global__ void __launch_bounds__(256) wh_kernel(const float* __restrict__ x,
                                                 const float* __restrict__ y)
{
    extern __shared__ float sm[];
    float* sx  = sm;                        // HR * SXP
    float* sy  = sm + HR*SXP;               // HR * SXP
    float* sp  = sm + 2*HR*SXP;             // 5 * HR * SPP  (W-summed products)
    float* red = sp + 5*HR*SPP;             // 256

    const int tid = threadIdx.x;
    const int th  = blockIdx.x;             // 0..4
    const int d   = blockIdx.y;             // 0..159
    const int b   = blockIdx.z;             // 0..1
    const int h0  = th * TH;
    const size_t base = ((size_t)b*DD + d) * SLICE;

    // ---- Stage 1: load halo'd slab, zero-pad, fused smooth-L1 on owned rows
    float l1acc = 0.f;
    for (int idx = tid; idx < HR*WW; idx += 256) {
        int r = idx / WW;
        int w = idx - r*WW;
        int gh = h0 - RAD + r;
        float xv = 0.f, yv = 0.f;
        if (gh >= 0 && gh < HH) {
            size_t g = base + (size_t)gh*WW + w;
            xv = x[g]; yv = y[g];
        }
        sx[r*SXP + w] = xv;
        sy[r*SXP + w] = yv;
        if (r >= RAD && r < RAD + TH) {
            float dq = fabsf(xv - yv);
            l1acc += (dq < 1.f) ? 0.5f*dq*dq : (dq - 0.5f);
        }
    }
    __syncthreads();

    // ---- Stage 2: sliding W-sum of the 5 products, per (segment, row) job
    for (int j = tid; j < 5*HR; j += 256) {
        int s = j / HR;                 // w-segment 0..4
        int r = j - s*HR;               // row 0..41
        int w0 = s * 32;
        const float* rx = sx + r*SXP;
        const float* ry = sy + r*SXP;
        float a0=0.f, a1=0.f, a2=0.f, a3=0.f, a4=0.f;
        #pragma unroll
        for (int k = -RAD; k <= RAD; k++) {
            int t = w0 + k;
            if (t >= 0 && t < WW) {
                float xv = rx[t], yv = ry[t];
                a0 += xv; a1 += yv; a2 += xv*xv; a3 += yv*yv; a4 += xv*yv;
            }
        }
        for (int w = w0; w < w0 + 32; w++) {
            sp[(0*HR + r)*SPP + w] = a0;
            sp[(1*HR + r)*SPP + w] = a1;
            sp[(2*HR + r)*SPP + w] = a2;
            sp[(3*HR + r)*SPP + w] = a3;
            sp[(4*HR + r)*SPP + w] = a4;
            int tin  = w + RAD + 1;
            int tout = w - RAD;
            if (tin < WW)  { float xv=rx[tin],  yv=ry[tin];
                             a0+=xv; a1+=yv; a2+=xv*xv; a3+=yv*yv; a4+=xv*yv; }
            if (tout >= 0) { float xv=rx[tout], yv=ry[tout];
                             a0-=xv; a1-=yv; a2-=xv*xv; a3-=yv*yv; a4-=xv*yv; }
        }
    }
    __syncthreads();

    // ---- Stage 3: sliding H-sum, write 5 fields to global scratch
    for (int j = tid; j < 5*WW; j += 256) {
        int f = j / WW;
        int w = j - f*WW;
        const float* col = sp + (f*HR)*SPP + w;
        float acc = 0.f;
        #pragma unroll
        for (int rr = 0; rr < WIN; rr++) acc += col[rr*SPP];
        float* gout = &g_swh[f][base];
        #pragma unroll 4
        for (int ro = 0; ro < TH; ro++) {
            gout[(size_t)(h0 + ro)*WW + w] = acc;
            if (ro < TH - 1) acc += col[(ro + WIN)*SPP] - col[ro*SPP];
        }
    }

    // ---- L1 block reduce
    red[tid] = l1acc;
    __syncthreads();
    for (int s2 = 128; s2 > 0; s2 >>= 1) {
        if (tid < s2) red[tid] += red[tid + s2];
        __syncthreads();
    }
    if (tid == 0) {
        int bid = blockIdx.x + 5*(blockIdx.y + DD*blockIdx.z);
        g_l1p[bid] = red[0];
    }
}

// ---------------------------------------------------------------------------
// Kernel 2: sliding D-sum per column, per-voxel SSIM, block-reduced partial.
// ---------------------------------------------------------------------------
__global__ void __launch_bounds__(256) dpass_kernel()
{
    const int gid   = blockIdx.x * 256 + threadIdx.x;   // 0..102399
    const int split = gid / NCOLS;                      // 0..NSPLIT-1
    const int col   = gid - split*NCOLS;                // 0..51199
    const int b     = col / SLICE;
    const int hw    = col - b*SLICE;
    const size_t base = (size_t)b*VOL + hw;

    const float* __restrict__ A0 = g_swh[0] + base;
    const float* __restrict__ A1 = g_swh[1] + base;
    const float* __restrict__ A2 = g_swh[2] + base;
    const float* __restrict__ A3 = g_swh[3] + base;
    const float* __restrict__ A4 = g_swh[4] + base;

    const int d0 = split * DR;
    float Sx=0.f, Sy=0.f, Sxx=0.f, Syy=0.f, Sxy=0.f;
    int tlo = d0 - RAD; if (tlo < 0) tlo = 0;
    for (int t = tlo; t <= d0 + RAD; t++) {
        size_t o = (size_t)t * SLICE;
        Sx += A0[o]; Sy += A1[o]; Sxx += A2[o]; Syy += A3[o]; Sxy += A4[o];
    }

    const float inv = 1.0f / 1331.0f;                 // 1/11^3
    const float C1  = 0.01f / (4096.f*4096.f);        // K1 / data_range^2 (faithful)
    const float C2  = 0.03f / (4096.f*4096.f);
    float acc = 0.f;

    for (int d = d0; d < d0 + DR; d++) {
        float mx  = Sx*inv,  my  = Sy*inv;
        float mx2 = mx*mx,   my2 = my*my,   mxy = mx*my;
        float vx  = Sxx*inv - mx2;
        float vy  = Syy*inv - my2;
        float vxy = Sxy*inv - mxy;
        float n  = (2.f*mxy + C1) * (2.f*vxy + C2);
        float de = (mx2 + my2 + C1) * (vx + vy + C2);
        float ss = n / (de + 1e-8f);
        float v  = 0.5f * (1.f - ss);
        v = fminf(fmaxf(v, 0.f), 1.f);
        acc += v;

        if (d < d0 + DR - 1) {
            int tin  = d + RAD + 1;
            int tout = d - RAD;
            if (tin < DD) {
                size_t o = (size_t)tin * SLICE;
                Sx += A0[o]; Sy += A1[o]; Sxx += A2[o]; Syy += A3[o]; Sxy += A4[o];
            }
            if (tout >= 0) {
                size_t o = (size_t)tout * SLICE;
                Sx -= A0[o]; Sy -= A1[o]; Sxx -= A2[o]; Syy -= A3[o]; Sxy -= A4[o];
            }
        }
    }

    __shared__ float red[256];
    red[threadIdx.x] = acc;
    __syncthreads();
    for (int s2 = 128; s2 > 0; s2 >>= 1) {
        if (threadIdx.x < s2) red[threadIdx.x] += red[threadIdx.x + s2];
        __syncthreads();
    }
    if (threadIdx.x == 0) g_ssimp[blockIdx.x] = red[0];
}

// ---------------------------------------------------------------------------
// Kernel 3: finalize in double precision.
// ---------------------------------------------------------------------------
__global__ void finalize_kernel(float* __restrict__ out)
{
    __shared__ double red[256];
    const int tid = threadIdx.x;

    double a = 0.0;
    for (int i = tid; i < NBLK1; i += 256) a += (double)g_l1p[i];
    red[tid] = a; __syncthreads();
    for (int s = 128; s > 0; s >>= 1) {
        if (tid < s) red[tid] += red[tid + s];
        __syncthreads();
    }
    double l1sum = red[0];
    __syncthreads();

    double c = 0.0;
    for (int i = tid; i < NBLK2; i += 256) c += (double)g_ssimp[i];
    red[tid] = c; __syncthreads();
    for (int s = 128; s > 0; s >>= 1) {
        if (tid < s) red[tid] += red[tid + s];
        __syncthreads();
    }
    if (tid == 0) {
        double ssim_mean = red[0] / (double)TOTAL;
        double l1_mean   = l1sum  / (double)TOTAL;
        out[0] = (float)(0.85 * ssim_mean + 0.15 * l1_mean);
    }
}

// ---------------------------------------------------------------------------
extern "C" void kernel_launch(void* const* d_in, const int* in_sizes, int n_in,
                              void* d_out, int out_size)
{
    const float* pred   = (const float*)d_in[0];
    const float* target = (const float*)d_in[1];
    float* out = (float*)d_out;

    const int smem_bytes = (2*HR*SXP + 5*HR*SPP + 256) * (int)sizeof(float); // 191,704 B
    cudaFuncSetAttribute(wh_kernel, cudaFuncAttributeMaxDynamicSharedMemorySize, smem_bytes);

    dim3 g1(5, DD, BB);   // 1600 blocks
    wh_kernel<<<g1, 256, smem_bytes>>>(pred, target);
    dpass_kernel<<<NBLK2, 256>>>();
    finalize_kernel<<<1, 256>>>(out);
}

// round 3
// speedup vs baseline: 1.6546x; 1.6546x over previous
#include <cuda_runtime.h>
#include <math.h>

// Problem constants
#define BB 2
#define DD 160
#define HH 160
#define WW 160
#define SLICE (HH*WW)          // 25600
#define VOL (DD*SLICE)         // 4096000
#define TOTAL (BB*VOL)         // 8192000
#define RAD 5
#define WIN 11
#define NF 4                   // Sx, Sy, Sq=Sxx+Syy, Sxy

#define TH 16                  // h-rows per tile in kernel 1
#define HR (TH + 2*RAD)        // 26 rows incl halo
#define STR 161                // unified smem row stride (odd -> conflict-free)
#define NTILE (HH/TH)          // 10
#define NBLK1 (NTILE*DD*BB)    // 3200 blocks in kernel 1

#define NSEG 8                 // w-segments in stage 2
#define SEGW (WW/NSEG)         // 20

#define NSPLIT 5
#define DR (DD/NSPLIT)         // 32 d-steps per thread in kernel 2
#define NCOLS (BB*SLICE)       // 51200 columns
#define NBLK2 ((NCOLS*NSPLIT)/256)  // 1000 blocks in kernel 2

// Global scratch: 4 box-summed (W,H) fields + reduction partials.
__device__ float g_swh[NF][TOTAL];
__device__ float g_l1p[NBLK1];
__device__ float g_ssimp[NBLK2];

// ---------------------------------------------------------------------------
// Kernel 1: per (b,d,h-tile): products + sliding W-sum + sliding H-sum.
// Also accumulates smooth-L1 partial over owned rows.
// SMEM: sx,sy slabs (HR x STR each) + NF product buffers (HR x STR each).
// ---------------------------------------------------------------------------
__global__ void __launch_bounds__(256, 2) wh_kernel(const float* __restrict__ x,
                                                    const float* __restrict__ y)
{
    extern __shared__ float sm[];
    float* sx = sm;                 // HR*STR
    float* sy = sm + HR*STR;        // HR*STR
    float* sp = sm + 2*HR*STR;      // NF * HR * STR  (W-summed products)
    __shared__ float red[256];

    const int tid = threadIdx.x;
    const int th  = blockIdx.x;             // 0..NTILE-1
    const int d   = blockIdx.y;             // 0..159
    const int b   = blockIdx.z;             // 0..1
    const int h0  = th * TH;
    const size_t base = ((size_t)b*DD + d) * SLICE;

    // ---- Stage 1: vectorized halo'd slab load + fused smooth-L1 on owned rows
    float l1acc = 0.f;
    const int W4 = WW/4;                    // 40
    for (int idx = tid; idx < HR*W4; idx += 256) {
        int r  = idx / W4;
        int w4 = idx - r*W4;
        int gh = h0 - RAD + r;
        float4 xv = make_float4(0.f,0.f,0.f,0.f);
        float4 yv = make_float4(0.f,0.f,0.f,0.f);
        if (gh >= 0 && gh < HH) {
            size_t g = (base + (size_t)gh*WW + w4*4) >> 2;
            xv = ((const float4*)x)[g];
            yv = ((const float4*)y)[g];
        }
        float* px = sx + r*STR + w4*4;
        float* py = sy + r*STR + w4*4;
        px[0]=xv.x; px[1]=xv.y; px[2]=xv.z; px[3]=xv.w;
        py[0]=yv.x; py[1]=yv.y; py[2]=yv.z; py[3]=yv.w;
        if (r >= RAD && r < RAD + TH) {
            float d0=fabsf(xv.x-yv.x), d1=fabsf(xv.y-yv.y);
            float d2=fabsf(xv.z-yv.z), d3=fabsf(xv.w-yv.w);
            l1acc += (d0<1.f)?0.5f*d0*d0:(d0-0.5f);
            l1acc += (d1<1.f)?0.5f*d1*d1:(d1-0.5f);
            l1acc += (d2<1.f)?0.5f*d2*d2:(d2-0.5f);
            l1acc += (d3<1.f)?0.5f*d3*d3:(d3-0.5f);
        }
    }
    __syncthreads();

    // ---- Stage 2: sliding W-sum of 4 product fields, (segment,row) jobs
    if (tid < NSEG*HR) {
        int s = tid / HR;               // w-segment
        int r = tid - s*HR;             // row 0..HR-1
        int w0 = s * SEGW;
        const float* rx = sx + r*STR;
        const float* ry = sy + r*STR;
        float a0=0.f, a1=0.f, a2=0.f, a3=0.f;
        #pragma unroll
        for (int k = -RAD; k <= RAD; k++) {
            int t = w0 + k;
            if (t >= 0 && t < WW) {
                float xv = rx[t], yv = ry[t];
                a0 += xv; a1 += yv; a2 += xv*xv + yv*yv; a3 += xv*yv;
            }
        }
        #pragma unroll 4
        for (int w = w0; w < w0 + SEGW; w++) {
            sp[(0*HR + r)*STR + w] = a0;
            sp[(1*HR + r)*STR + w] = a1;
            sp[(2*HR + r)*STR + w] = a2;
            sp[(3*HR + r)*STR + w] = a3;
            int tin  = w + RAD + 1;
            int tout = w - RAD;
            if (tin < WW)  { float xv=rx[tin],  yv=ry[tin];
                             a0+=xv; a1+=yv; a2+=xv*xv+yv*yv; a3+=xv*yv; }
            if (tout >= 0) { float xv=rx[tout], yv=ry[tout];
                             a0-=xv; a1-=yv; a2-=xv*xv+yv*yv; a3-=xv*yv; }
        }
    }
    __syncthreads();

    // ---- Stage 3: sliding H-sum, write 4 fields to global scratch
    for (int j = tid; j < NF*WW; j += 256) {
        int f = j / WW;
        int w = j - f*WW;
        const float* col = sp + (f*HR)*STR + w;
        float acc = 0.f;
        #pragma unroll
        for (int rr = 0; rr < WIN; rr++) acc += col[rr*STR];
        float* gout = &g_swh[f][base];
        #pragma unroll
        for (int ro = 0; ro < TH; ro++) {
            gout[(size_t)(h0 + ro)*WW + w] = acc;
            if (ro < TH - 1) acc += col[(ro + WIN)*STR] - col[ro*STR];
        }
    }

    // ---- L1 block reduce
    red[tid] = l1acc;
    __syncthreads();
    for (int s2 = 128; s2 > 0; s2 >>= 1) {
        if (tid < s2) red[tid] += red[tid + s2];
        __syncthreads();
    }
    if (tid == 0) {
        int bid = blockIdx.x + NTILE*(blockIdx.y + DD*blockIdx.z);
        g_l1p[bid] = red[0];
    }
}

// ---------------------------------------------------------------------------
// Kernel 2: sliding D-sum per column, per-voxel SSIM, block-reduced partial.
// ---------------------------------------------------------------------------
__global__ void __launch_bounds__(256) dpass_kernel()
{
    const int gid   = blockIdx.x * 256 + threadIdx.x;
    const int split = gid / NCOLS;
    const int col   = gid - split*NCOLS;
    const int b     = col / SLICE;
    const int hw    = col - b*SLICE;
    const size_t base = (size_t)b*VOL + hw;

    const float* __restrict__ A0 = g_swh[0] + base;
    const float* __restrict__ A1 = g_swh[1] + base;
    const float* __restrict__ A2 = g_swh[2] + base;
    const float* __restrict__ A3 = g_swh[3] + base;

    const int d0 = split * DR;
    float Sx=0.f, Sy=0.f, Sq=0.f, Sxy=0.f;
    int tlo = d0 - RAD; if (tlo < 0) tlo = 0;
    for (int t = tlo; t <= d0 + RAD; t++) {
        size_t o = (size_t)t * SLICE;
        Sx += A0[o]; Sy += A1[o]; Sq += A2[o]; Sxy += A3[o];
    }

    const float inv = 1.0f / 1331.0f;                 // 1/11^3
    const float C1  = 0.01f / (4096.f*4096.f);        // K1 / data_range^2 (faithful)
    const float C2  = 0.03f / (4096.f*4096.f);
    float acc = 0.f;

    for (int d = d0; d < d0 + DR; d++) {
        float mx  = Sx*inv,  my  = Sy*inv;
        float mx2 = mx*mx,   my2 = my*my,   mxy = mx*my;
        float vsum = Sq*inv - mx2 - my2;              // sigma_x2 + sigma_y2
        float vxy  = Sxy*inv - mxy;
        float n  = (2.f*mxy + C1) * (2.f*vxy + C2);
        float de = (mx2 + my2 + C1) * (vsum + C2);
        float ss = n / (de + 1e-8f);
        float v  = 0.5f * (1.f - ss);
        v = fminf(fmaxf(v, 0.f), 1.f);
        acc += v;

        if (d < d0 + DR - 1) {
            int tin  = d + RAD + 1;
            int tout = d - RAD;
            if (tin < DD) {
                size_t o = (size_t)tin * SLICE;
                Sx += A0[o]; Sy += A1[o]; Sq += A2[o]; Sxy += A3[o];
            }
            if (tout >= 0) {
                size_t o = (size_t)tout * SLICE;
                Sx -= A0[o]; Sy -= A1[o]; Sq -= A2[o]; Sxy -= A3[o];
            }
        }
    }

    __shared__ float red[256];
    red[threadIdx.x] = acc;
    __syncthreads();
    for (int s2 = 128; s2 > 0; s2 >>= 1) {
        if (threadIdx.x < s2) red[threadIdx.x] += red[threadIdx.x + s2];
        __syncthreads();
    }
    if (threadIdx.x == 0) g_ssimp[blockIdx.x] = red[0];
}

// ---------------------------------------------------------------------------
// Kernel 3: finalize in double precision.
// ---------------------------------------------------------------------------
__global__ void finalize_kernel(float* __restrict__ out)
{
    __shared__ double red[256];
    const int tid = threadIdx.x;

    double a = 0.0;
    for (int i = tid; i < NBLK1; i += 256) a += (double)g_l1p[i];
    red[tid] = a; __syncthreads();
    for (int s = 128; s > 0; s >>= 1) {
        if (tid < s) red[tid] += red[tid + s];
        __syncthreads();
    }
    double l1sum = red[0];
    __syncthreads();

    double c = 0.0;
    for (int i = tid; i < NBLK2; i += 256) c += (double)g_ssimp[i];
    red[tid] = c; __syncthreads();
    for (int s = 128; s > 0; s >>= 1) {
        if (tid < s) red[tid] += red[tid + s];
        __syncthreads();
    }
    if (tid == 0) {
        double ssim_mean = red[0] / (double)TOTAL;
        double l1_mean   = l1sum  / (double)TOTAL;
        out[0] = (float)(0.85 * ssim_mean + 0.15 * l1_mean);
    }
}

// ---------------------------------------------------------------------------
extern "C" void kernel_launch(void* const* d_in, const int* in_sizes, int n_in,
                              void* d_out, int out_size)
{
    const float* pred   = (const float*)d_in[0];
    const float* target = (const float*)d_in[1];
    float* out = (float*)d_out;

    const int smem_bytes = ((2 + NF)*HR*STR) * (int)sizeof(float); // 100,464 B
    cudaFuncSetAttribute(wh_kernel, cudaFuncAttributeMaxDynamicSharedMemorySize, smem_bytes);

    dim3 g1(NTILE, DD, BB);   // 3200 blocks
    wh_kernel<<<g1, 256, smem_bytes>>>(pred, target);
    dpass_kernel<<<NBLK2, 256>>>();
    finalize_kernel<<<1, 256>>>(out);
}

// round 6
// speedup vs baseline: 1.7575x; 1.0622x over previous
#include <cuda_runtime.h>
#include <math.h>

// Problem constants
#define BB 2
#define DD 160
#define HH 160
#define WW 160
#define SLICE (HH*WW)          // 25600
#define VOL (DD*SLICE)         // 4096000
#define TOTAL (BB*VOL)         // 8192000
#define RAD 5
#define WIN 11
#define NF 4                   // Sx, Sy, Sq=Sxx+Syy, Sxy

#define TH 16                  // h-rows per tile in kernel 1
#define HR (TH + 2*RAD)        // 26 rows incl halo
#define STR 161                // unified smem row stride (odd -> conflict-free)
#define NTILE (HH/TH)          // 10
#define NBLK1 (NTILE*DD*BB)    // 3200 blocks in kernel 1

#define NSEG 8                 // w-segments in stage 2
#define SEGW (WW/NSEG)         // 20

#define NSPLIT 5
#define DR (DD/NSPLIT)         // 32 d-steps per thread in kernel 2
#define NCOLS (BB*SLICE)       // 51200 columns
#define TPB2 128
#define NTH2 ((NCOLS/4)*NSPLIT)     // 64000 threads in kernel 2
#define NBLK2 (NTH2/TPB2)           // 500 blocks

// SSIM constants in raw-sum space (multiplied through by 1331^4)
#define C1S 1.0559354e-3f           // 0.01/4096^2 * 1331^2
#define C2S 3.1678061e-3f           // 0.03/4096^2 * 1331^2
#define EPSS 31384.2838f            // 1e-8 * 1331^4

// Global scratch: 4 box-summed (W,H) fields + reduction partials.
__device__ float g_swh[NF][TOTAL];
__device__ float g_l1p[NBLK1];
__device__ float g_ssimp[NBLK2];

// ---------------------------------------------------------------------------
// Kernel 1: per (b,d,h-tile): products + sliding W-sum + sliding H-sum.
// Register rings in both sliding scans avoid SMEM re-reads.
// ---------------------------------------------------------------------------
__global__ void __launch_bounds__(256, 2) wh_kernel(const float* __restrict__ x,
                                                    const float* __restrict__ y)
{
    extern __shared__ float sm[];
    float* sx = sm;                 // HR*STR
    float* sy = sm + HR*STR;        // HR*STR
    float* sp = sm + 2*HR*STR;      // NF * HR * STR  (W-summed products)
    __shared__ float red[256];

    const int tid = threadIdx.x;
    const int th  = blockIdx.x;             // 0..NTILE-1
    const int d   = blockIdx.y;             // 0..159
    const int b   = blockIdx.z;             // 0..1
    const int h0  = th * TH;
    const size_t base = ((size_t)b*DD + d) * SLICE;

    // ---- Stage 1: vectorized halo'd slab load + fused smooth-L1 on owned rows
    float l1acc = 0.f;
    const int W4 = WW/4;                    // 40
    for (int idx = tid; idx < HR*W4; idx += 256) {
        int r  = idx / W4;
        int w4 = idx - r*W4;
        int gh = h0 - RAD + r;
        float4 xv = make_float4(0.f,0.f,0.f,0.f);
        float4 yv = make_float4(0.f,0.f,0.f,0.f);
        if (gh >= 0 && gh < HH) {
            size_t g = (base + (size_t)gh*WW + w4*4) >> 2;
            xv = ((const float4*)x)[g];
            yv = ((const float4*)y)[g];
        }
        float* px = sx + r*STR + w4*4;
        float* py = sy + r*STR + w4*4;
        px[0]=xv.x; px[1]=xv.y; px[2]=xv.z; px[3]=xv.w;
        py[0]=yv.x; py[1]=yv.y; py[2]=yv.z; py[3]=yv.w;
        if (r >= RAD && r < RAD + TH) {
            float d0=fabsf(xv.x-yv.x), d1=fabsf(xv.y-yv.y);
            float d2=fabsf(xv.z-yv.z), d3=fabsf(xv.w-yv.w);
            l1acc += (d0<1.f)?0.5f*d0*d0:(d0-0.5f);
            l1acc += (d1<1.f)?0.5f*d1*d1:(d1-0.5f);
            l1acc += (d2<1.f)?0.5f*d2*d2:(d2-0.5f);
            l1acc += (d3<1.f)?0.5f*d3*d3:(d3-0.5f);
        }
    }
    __syncthreads();

    // ---- Stage 2: sliding W-sum of 4 product fields, register ring depth 11
    if (tid < NSEG*HR) {
        int s = tid / HR;               // w-segment
        int r = tid - s*HR;             // row 0..HR-1
        int w0 = s * SEGW;
        const float* rx = sx + r*STR;
        const float* ry = sy + r*STR;
        float xr[WIN], yr[WIN];
        float a0=0.f, a1=0.f, a2=0.f, a3=0.f;
        #pragma unroll
        for (int i = 0; i < WIN; i++) {
            int t = w0 - RAD + i;
            float xv = 0.f, yv = 0.f;
            if (t >= 0) { xv = rx[t]; yv = ry[t]; }   // t < WW always (w0<=140, i<=10)
            xr[i] = xv; yr[i] = yv;
            a0 += xv; a1 += yv; a2 += xv*xv + yv*yv; a3 += xv*yv;
        }
        float* sp0 = sp + (0*HR + r)*STR;
        float* sp1 = sp + (1*HR + r)*STR;
        float* sp2 = sp + (2*HR + r)*STR;
        float* sp3 = sp + (3*HR + r)*STR;
        #pragma unroll
        for (int k = 0; k < SEGW; k++) {
            int w = w0 + k;
            sp0[w] = a0; sp1[w] = a1; sp2[w] = a2; sp3[w] = a3;
            // subtract outgoing (w-RAD), pushed 11 iters ago at slot k%WIN
            float xo = xr[k%WIN], yo = yr[k%WIN];
            a0 -= xo; a1 -= yo; a2 -= xo*xo + yo*yo; a3 -= xo*yo;
            // add incoming (w+RAD+1)
            int tin = w + RAD + 1;
            float xv = 0.f, yv = 0.f;
            if (tin < WW) { xv = rx[tin]; yv = ry[tin]; }
            xr[k%WIN] = xv; yr[k%WIN] = yv;
            a0 += xv; a1 += yv; a2 += xv*xv + yv*yv; a3 += xv*yv;
        }
    }
    __syncthreads();

    // ---- Stage 3: sliding H-sum with register ring, write 4 fields to scratch
    for (int j = tid; j < NF*WW; j += 256) {
        int f = j / WW;
        int w = j - f*WW;
        const float* col = sp + (f*HR)*STR + w;
        float ring[WIN];
        float acc = 0.f;
        #pragma unroll
        for (int i = 0; i < WIN; i++) {
            float v = col[i*STR];
            ring[i] = v;
            acc += v;
        }
        float* gout = &g_swh[f][base + (size_t)h0*WW + w];
        #pragma unroll
        for (int ro = 0; ro < TH; ro++) {
            gout[(size_t)ro*WW] = acc;
            if (ro < TH - 1) {
                float vin = col[(ro + WIN)*STR];
                acc += vin - ring[ro%WIN];
                ring[ro%WIN] = vin;
            }
        }
    }

    // ---- L1 block reduce
    red[tid] = l1acc;
    __syncthreads();
    for (int s2 = 128; s2 > 0; s2 >>= 1) {
        if (tid < s2) red[tid] += red[tid + s2];
        __syncthreads();
    }
    if (tid == 0) {
        int bid = blockIdx.x + NTILE*(blockIdx.y + DD*blockIdx.z);
        g_l1p[bid] = red[0];
    }
}

// ---------------------------------------------------------------------------
// Kernel 2: sliding D-sum per 4-column group (float4), raw-sum SSIM math.
// ---------------------------------------------------------------------------
__device__ __forceinline__ float ssim_elem(float Sx, float Sy, float Sq, float Sxy)
{
    float q  = 2.f * Sx * Sy;
    float T  = Sx*Sx + Sy*Sy;
    float N1 = q + C1S;
    float N2 = fmaf(2662.f, Sxy, C2S - q);
    float D1 = T + C1S;
    float D2 = fmaf(1331.f, Sq, C2S - T);
    float ss = __fdividef(N1*N2, fmaf(D1, D2, EPSS));
    float v  = 0.5f - 0.5f*ss;
    return fminf(fmaxf(v, 0.f), 1.f);
}

__global__ void __launch_bounds__(TPB2) dpass_kernel()
{
    const int gid   = blockIdx.x * TPB2 + threadIdx.x;   // 0..NTH2-1
    const int QC    = NCOLS/4;                           // 12800
    const int split = gid / QC;
    const int c4    = gid - split*QC;
    const int col   = c4 * 4;
    const int b     = col / SLICE;
    const int hw    = col - b*SLICE;
    const size_t base4 = ((size_t)b*VOL + hw) >> 2;      // float4 index
    const int S4 = SLICE/4;                              // 6400

    const float4* __restrict__ A0 = ((const float4*)g_swh[0]) + base4;
    const float4* __restrict__ A1 = ((const float4*)g_swh[1]) + base4;
    const float4* __restrict__ A2 = ((const float4*)g_swh[2]) + base4;
    const float4* __restrict__ A3 = ((const float4*)g_swh[3]) + base4;

    const int d0 = split * DR;
    float4 Sx = make_float4(0,0,0,0), Sy = Sx, Sq = Sx, Sxy = Sx;
    int tlo = d0 - RAD; if (tlo < 0) tlo = 0;
    for (int t = tlo; t <= d0 + RAD; t++) {
        size_t o = (size_t)t * S4;
        float4 a = A0[o], bb4 = A1[o], c = A2[o], e = A3[o];
        Sx.x+=a.x; Sx.y+=a.y; Sx.z+=a.z; Sx.w+=a.w;
        Sy.x+=bb4.x; Sy.y+=bb4.y; Sy.z+=bb4.z; Sy.w+=bb4.w;
        Sq.x+=c.x; Sq.y+=c.y; Sq.z+=c.z; Sq.w+=c.w;
        Sxy.x+=e.x; Sxy.y+=e.y; Sxy.z+=e.z; Sxy.w+=e.w;
    }

    float acc = 0.f;
    for (int d = d0; d < d0 + DR; d++) {
        acc += ssim_elem(Sx.x, Sy.x, Sq.x, Sxy.x);
        acc += ssim_elem(Sx.y, Sy.y, Sq.y, Sxy.y);
        acc += ssim_elem(Sx.z, Sy.z, Sq.z, Sxy.z);
        acc += ssim_elem(Sx.w, Sy.w, Sq.w, Sxy.w);

        if (d < d0 + DR - 1) {
            int tin  = d + RAD + 1;
            int tout = d - RAD;
            if (tin < DD) {
                size_t o = (size_t)tin * S4;
                float4 a = A0[o], bb4 = A1[o], c = A2[o], e = A3[o];
                Sx.x+=a.x; Sx.y+=a.y; Sx.z+=a.z; Sx.w+=a.w;
                Sy.x+=bb4.x; Sy.y+=bb4.y; Sy.z+=bb4.z; Sy.w+=bb4.w;
                Sq.x+=c.x; Sq.y+=c.y; Sq.z+=c.z; Sq.w+=c.w;
                Sxy.x+=e.x; Sxy.y+=e.y; Sxy.z+=e.z; Sxy.w+=e.w;
            }
            if (tout >= 0) {
                size_t o = (size_t)tout * S4;
                float4 a = A0[o], bb4 = A1[o], c = A2[o], e = A3[o];
                Sx.x-=a.x; Sx.y-=a.y; Sx.z-=a.z; Sx.w-=a.w;
                Sy.x-=bb4.x; Sy.y-=bb4.y; Sy.z-=bb4.z; Sy.w-=bb4.w;
                Sq.x-=c.x; Sq.y-=c.y; Sq.z-=c.z; Sq.w-=c.w;
                Sxy.x-=e.x; Sxy.y-=e.y; Sxy.z-=e.z; Sxy.w-=e.w;
            }
        }
    }

    __shared__ float red[TPB2];
    red[threadIdx.x] = acc;
    __syncthreads();
    for (int s2 = TPB2/2; s2 > 0; s2 >>= 1) {
        if (threadIdx.x < s2) red[threadIdx.x] += red[threadIdx.x + s2];
        __syncthreads();
    }
    if (threadIdx.x == 0) g_ssimp[blockIdx.x] = red[0];
}

// ---------------------------------------------------------------------------
// Kernel 3: finalize in double precision.
// ---------------------------------------------------------------------------
__global__ void finalize_kernel(float* __restrict__ out)
{
    __shared__ double red[256];
    const int tid = threadIdx.x;

    double a = 0.0;
    for (int i = tid; i < NBLK1; i += 256) a += (double)g_l1p[i];
    red[tid] = a; __syncthreads();
    for (int s = 128; s > 0; s >>= 1) {
        if (tid < s) red[tid] += red[tid + s];
        __syncthreads();
    }
    double l1sum = red[0];
    __syncthreads();

    double c = 0.0;
    for (int i = tid; i < NBLK2; i += 256) c += (double)g_ssimp[i];
    red[tid] = c; __syncthreads();
    for (int s = 128; s > 0; s >>= 1) {
        if (tid < s) red[tid] += red[tid + s];
        __syncthreads();
    }
    if (tid == 0) {
        double ssim_mean = red[0] / (double)TOTAL;
        double l1_mean   = l1sum  / (double)TOTAL;
        out[0] = (float)(0.85 * ssim_mean + 0.15 * l1_mean);
    }
}

// ---------------------------------------------------------------------------
extern "C" void kernel_launch(void* const* d_in, const int* in_sizes, int n_in,
                              void* d_out, int out_size)
{
    const float* pred   = (const float*)d_in[0];
    const float* target = (const float*)d_in[1];
    float* out = (float*)d_out;

    const int smem_bytes = ((2 + NF)*HR*STR) * (int)sizeof(float); // 100,464 B
    cudaFuncSetAttribute(wh_kernel, cudaFuncAttributeMaxDynamicSharedMemorySize, smem_bytes);

    dim3 g1(NTILE, DD, BB);   // 3200 blocks
    wh_kernel<<<g1, 256, smem_bytes>>>(pred, target);
    dpass_kernel<<<NBLK2, TPB2>>>();
    finalize_kernel<<<1, 256>>>(out);
}

// round 7
// speedup vs baseline: 2.3031x; 1.3104x over previous
#include <cuda_runtime.h>
#include <cuda_fp16.h>
#include <math.h>

// Problem constants
#define BB 2
#define DD 160
#define HH 160
#define WW 160
#define SLICE (HH*WW)          // 25600
#define VOL (DD*SLICE)         // 4096000
#define TOTAL (BB*VOL)         // 8192000
#define RAD 5
#define WIN 11
#define NF 4                   // Sx, Sy, Sq=Sxx+Syy, Sxy

#define TH 16                  // h-rows per tile in kernel 1
#define HR (TH + 2*RAD)        // 26 rows incl halo
#define STR 161                // smem float row stride (odd -> conflict-free)
#define STRH 163               // smem half row stride (odd)
#define NTILE (HH/TH)          // 10
#define NBLK1 (NTILE*DD*BB)    // 3200 blocks in kernel 1

#define NSEG 8                 // w-segments in stage 2
#define SEGW (WW/NSEG)         // 20

#define NSPLIT 8
#define DR (DD/NSPLIT)         // 20 d-steps per thread in kernel 2
#define NCOLS (BB*SLICE)       // 51200 columns
#define TPB2 256
#define NTH2 ((NCOLS/4)*NSPLIT)     // 102400 threads in kernel 2
#define NBLK2 (NTH2/TPB2)           // 400 blocks

// SSIM constants in raw-sum space (multiplied through by 1331^4)
#define C1S 1.0559354e-3f           // 0.01/4096^2 * 1331^2
#define C2S 3.1678061e-3f           // 0.03/4096^2 * 1331^2
#define EPSS 31384.2838f            // 1e-8 * 1331^4

// Global scratch: 4 half-precision box-summed (W,H) fields + partials.
__device__ __half g_swh[NF][TOTAL];
__device__ float g_l1p[NBLK1];
__device__ float g_ssimp[NBLK2];

// ---------------------------------------------------------------------------
// Kernel 1: per (b,d,h-tile): products + sliding W-sum + sliding H-sum.
// sp buffer and global output in fp16 to halve crossbar/DRAM bytes.
// ---------------------------------------------------------------------------
__global__ void __launch_bounds__(256, 3) wh_kernel(const float* __restrict__ x,
                                                    const float* __restrict__ y)
{
    extern __shared__ float sm[];
    float*  sx = sm;                           // HR*STR floats
    float*  sy = sm + HR*STR;                  // HR*STR floats
    __half* sp = (__half*)(sm + 2*HR*STR);     // NF*HR*STRH halves
    __shared__ float red[256];

    const int tid = threadIdx.x;
    const int th  = blockIdx.x;             // 0..NTILE-1
    const int d   = blockIdx.y;             // 0..159
    const int b   = blockIdx.z;             // 0..1
    const int h0  = th * TH;
    const size_t base = ((size_t)b*DD + d) * SLICE;

    // ---- Stage 1: vectorized halo'd slab load + fused smooth-L1 on owned rows
    float l1acc = 0.f;
    const int W4 = WW/4;                    // 40
    for (int idx = tid; idx < HR*W4; idx += 256) {
        int r  = idx / W4;
        int w4 = idx - r*W4;
        int gh = h0 - RAD + r;
        float4 xv = make_float4(0.f,0.f,0.f,0.f);
        float4 yv = make_float4(0.f,0.f,0.f,0.f);
        if (gh >= 0 && gh < HH) {
            size_t g = (base + (size_t)gh*WW + w4*4) >> 2;
            xv = ((const float4*)x)[g];
            yv = ((const float4*)y)[g];
        }
        float* px = sx + r*STR + w4*4;
        float* py = sy + r*STR + w4*4;
        px[0]=xv.x; px[1]=xv.y; px[2]=xv.z; px[3]=xv.w;
        py[0]=yv.x; py[1]=yv.y; py[2]=yv.z; py[3]=yv.w;
        if (r >= RAD && r < RAD + TH) {
            float d0=fabsf(xv.x-yv.x), d1=fabsf(xv.y-yv.y);
            float d2=fabsf(xv.z-yv.z), d3=fabsf(xv.w-yv.w);
            l1acc += (d0<1.f)?0.5f*d0*d0:(d0-0.5f);
            l1acc += (d1<1.f)?0.5f*d1*d1:(d1-0.5f);
            l1acc += (d2<1.f)?0.5f*d2*d2:(d2-0.5f);
            l1acc += (d3<1.f)?0.5f*d3*d3:(d3-0.5f);
        }
    }
    __syncthreads();

    // ---- Stage 2: sliding W-sum of 4 product fields, register ring depth 11
    if (tid < NSEG*HR) {
        int s = tid / HR;               // w-segment
        int r = tid - s*HR;             // row 0..HR-1
        int w0 = s * SEGW;
        const float* rx = sx + r*STR;
        const float* ry = sy + r*STR;
        float xr[WIN], yr[WIN];
        float a0=0.f, a1=0.f, a2=0.f, a3=0.f;
        #pragma unroll
        for (int i = 0; i < WIN; i++) {
            int t = w0 - RAD + i;
            float xv = 0.f, yv = 0.f;
            if (t >= 0) { xv = rx[t]; yv = ry[t]; }   // t < WW always
            xr[i] = xv; yr[i] = yv;
            a0 += xv; a1 += yv; a2 += xv*xv + yv*yv; a3 += xv*yv;
        }
        __half* sp0 = sp + (0*HR + r)*STRH;
        __half* sp1 = sp + (1*HR + r)*STRH;
        __half* sp2 = sp + (2*HR + r)*STRH;
        __half* sp3 = sp + (3*HR + r)*STRH;
        #pragma unroll
        for (int k = 0; k < SEGW; k++) {
            int w = w0 + k;
            sp0[w] = __float2half_rn(a0);
            sp1[w] = __float2half_rn(a1);
            sp2[w] = __float2half_rn(a2);
            sp3[w] = __float2half_rn(a3);
            float xo = xr[k%WIN], yo = yr[k%WIN];
            a0 -= xo; a1 -= yo; a2 -= xo*xo + yo*yo; a3 -= xo*yo;
            int tin = w + RAD + 1;
            float xv = 0.f, yv = 0.f;
            if (tin < WW) { xv = rx[tin]; yv = ry[tin]; }
            xr[k%WIN] = xv; yr[k%WIN] = yv;
            a0 += xv; a1 += yv; a2 += xv*xv + yv*yv; a3 += xv*yv;
        }
    }
    __syncthreads();

    // ---- Stage 3: sliding H-sum with register ring, write fp16 fields
    for (int j = tid; j < NF*WW; j += 256) {
        int f = j / WW;
        int w = j - f*WW;
        const __half* col = sp + (f*HR)*STRH + w;
        float ring[WIN];
        float acc = 0.f;
        #pragma unroll
        for (int i = 0; i < WIN; i++) {
            float v = __half2float(col[i*STRH]);
            ring[i] = v;
            acc += v;
        }
        __half* gout = &g_swh[f][base + (size_t)h0*WW + w];
        #pragma unroll
        for (int ro = 0; ro < TH; ro++) {
            gout[(size_t)ro*WW] = __float2half_rn(acc);
            if (ro < TH - 1) {
                float vin = __half2float(col[(ro + WIN)*STRH]);
                acc += vin - ring[ro%WIN];
                ring[ro%WIN] = vin;
            }
        }
    }

    // ---- L1 block reduce
    red[tid] = l1acc;
    __syncthreads();
    for (int s2 = 128; s2 > 0; s2 >>= 1) {
        if (tid < s2) red[tid] += red[tid + s2];
        __syncthreads();
    }
    if (tid == 0) {
        int bid = blockIdx.x + NTILE*(blockIdx.y + DD*blockIdx.z);
        g_l1p[bid] = red[0];
    }
}

// ---------------------------------------------------------------------------
// Kernel 2: sliding D-sum over 4 half columns/thread, raw-sum SSIM math.
// ---------------------------------------------------------------------------
__device__ __forceinline__ float ssim_elem(float Sx, float Sy, float Sq, float Sxy)
{
    float q  = 2.f * Sx * Sy;
    float T  = Sx*Sx + Sy*Sy;
    float N1 = q + C1S;
    float N2 = fmaf(2662.f, Sxy, C2S - q);
    float D1 = T + C1S;
    float D2 = fmaf(1331.f, Sq, C2S - T);
    float ss = __fdividef(N1*N2, fmaf(D1, D2, EPSS));
    float v  = 0.5f - 0.5f*ss;
    return fminf(fmaxf(v, 0.f), 1.f);
}

__device__ __forceinline__ void unpack4(uint2 u, float* f)
{
    __half2 lo = *reinterpret_cast<__half2*>(&u.x);
    __half2 hi = *reinterpret_cast<__half2*>(&u.y);
    float2 a = __half22float2(lo);
    float2 c = __half22float2(hi);
    f[0]=a.x; f[1]=a.y; f[2]=c.x; f[3]=c.y;
}

__global__ void __launch_bounds__(TPB2) dpass_kernel()
{
    const int gid   = blockIdx.x * TPB2 + threadIdx.x;   // 0..NTH2-1
    const int QC    = NCOLS/4;                           // 12800
    const int split = gid / QC;
    const int c4    = gid - split*QC;
    const int col   = c4 * 4;
    const int b     = col / SLICE;
    const int hw    = col - b*SLICE;
    const size_t b4 = ((size_t)b*VOL + hw) >> 2;         // uint2 index
    const int S4 = SLICE/4;                              // 6400

    const uint2* __restrict__ A0 = (const uint2*)g_swh[0];
    const uint2* __restrict__ A1 = (const uint2*)g_swh[1];
    const uint2* __restrict__ A2 = (const uint2*)g_swh[2];
    const uint2* __restrict__ A3 = (const uint2*)g_swh[3];

    float Sx[4]  = {0,0,0,0};
    float Sy[4]  = {0,0,0,0};
    float Sq[4]  = {0,0,0,0};
    float Sxy[4] = {0,0,0,0};

    const int d0 = split * DR;
    int tlo = d0 - RAD; if (tlo < 0) tlo = 0;
    for (int t = tlo; t <= d0 + RAD; t++) {
        size_t o = b4 + (size_t)t * S4;
        float f0[4], f1[4], f2[4], f3[4];
        unpack4(A0[o], f0); unpack4(A1[o], f1);
        unpack4(A2[o], f2); unpack4(A3[o], f3);
        #pragma unroll
        for (int i = 0; i < 4; i++) {
            Sx[i]+=f0[i]; Sy[i]+=f1[i]; Sq[i]+=f2[i]; Sxy[i]+=f3[i];
        }
    }

    float acc = 0.f;
    for (int d = d0; d < d0 + DR; d++) {
        #pragma unroll
        for (int i = 0; i < 4; i++)
            acc += ssim_elem(Sx[i], Sy[i], Sq[i], Sxy[i]);

        if (d < d0 + DR - 1) {
            int tin  = d + RAD + 1;
            int tout = d - RAD;
            if (tin < DD) {
                size_t o = b4 + (size_t)tin * S4;
                float f0[4], f1[4], f2[4], f3[4];
                unpack4(A0[o], f0); unpack4(A1[o], f1);
                unpack4(A2[o], f2); unpack4(A3[o], f3);
                #pragma unroll
                for (int i = 0; i < 4; i++) {
                    Sx[i]+=f0[i]; Sy[i]+=f1[i]; Sq[i]+=f2[i]; Sxy[i]+=f3[i];
                }
            }
            if (tout >= 0) {
                size_t o = b4 + (size_t)tout * S4;
                float f0[4], f1[4], f2[4], f3[4];
                unpack4(A0[o], f0); unpack4(A1[o], f1);
                unpack4(A2[o], f2); unpack4(A3[o], f3);
                #pragma unroll
                for (int i = 0; i < 4; i++) {
                    Sx[i]-=f0[i]; Sy[i]-=f1[i]; Sq[i]-=f2[i]; Sxy[i]-=f3[i];
                }
            }
        }
    }

    __shared__ float red[TPB2];
    red[threadIdx.x] = acc;
    __syncthreads();
    for (int s2 = TPB2/2; s2 > 0; s2 >>= 1) {
        if (threadIdx.x < s2) red[threadIdx.x] += red[threadIdx.x + s2];
        __syncthreads();
    }
    if (threadIdx.x == 0) g_ssimp[blockIdx.x] = red[0];
}

// ---------------------------------------------------------------------------
// Kernel 3: finalize in double precision.
// ---------------------------------------------------------------------------
__global__ void finalize_kernel(float* __restrict__ out)
{
    __shared__ double red[256];
    const int tid = threadIdx.x;

    double a = 0.0;
    for (int i = tid; i < NBLK1; i += 256) a += (double)g_l1p[i];
    red[tid] = a; __syncthreads();
    for (int s = 128; s > 0; s >>= 1) {
        if (tid < s) red[tid] += red[tid + s];
        __syncthreads();
    }
    double l1sum = red[0];
    __syncthreads();

    double c = 0.0;
    for (int i = tid; i < NBLK2; i += 256) c += (double)g_ssimp[i];
    red[tid] = c; __syncthreads();
    for (int s = 128; s > 0; s >>= 1) {
        if (tid < s) red[tid] += red[tid + s];
        __syncthreads();
    }
    if (tid == 0) {
        double ssim_mean = red[0] / (double)TOTAL;
        double l1_mean   = l1sum  / (double)TOTAL;
        out[0] = (float)(0.85 * ssim_mean + 0.15 * l1_mean);
    }
}

// ---------------------------------------------------------------------------
extern "C" void kernel_launch(void* const* d_in, const int* in_sizes, int n_in,
                              void* d_out, int out_size)
{
    const float* pred   = (const float*)d_in[0];
    const float* target = (const float*)d_in[1];
    float* out = (float*)d_out;

    // dynamic smem: 2 float slabs + 4 half product buffers
    const int smem_bytes = 2*HR*STR*(int)sizeof(float) + NF*HR*STRH*(int)sizeof(__half); // 67,392 B
    cudaFuncSetAttribute(wh_kernel, cudaFuncAttributeMaxDynamicSharedMemorySize, smem_bytes);

    dim3 g1(NTILE, DD, BB);   // 3200 blocks
    wh_kernel<<<g1, 256, smem_bytes>>>(pred, target);
    dpass_kernel<<<NBLK2, TPB2>>>();
    finalize_kernel<<<1, 256>>>(out);
}

// round 8
// speedup vs baseline: 2.8706x; 1.2464x over previous
#include <cuda_runtime.h>
#include <cuda_fp16.h>
#include <math.h>

// Problem constants
#define BB 2
#define DD 160
#define HH 160
#define WW 160
#define SLICE (HH*WW)          // 25600
#define VOL (DD*SLICE)         // 4096000
#define TOTAL (BB*VOL)         // 8192000
#define RAD 5
#define WIN 11

#define TH 16                  // h-rows per tile in kernel 1
#define HR (TH + 2*RAD)        // 26 rows incl halo
#define SF2 161                // slab stride in float2 units (odd -> conflict-free)
#define SPU 161                // product plane stride in uint(half2) units (odd)
#define NTILE (HH/TH)          // 10
#define NBLK1 (NTILE*DD*BB)    // 3200 blocks in kernel 1

#define NSEG 8                 // w-segments in stage 2
#define SEGW (WW/NSEG)         // 20

#define NSPLIT 8
#define DR (DD/NSPLIT)         // 20 d-steps per thread in kernel 2
#define NCOLS (BB*SLICE)       // 51200 columns
#define TPB2 256
#define NTH2 ((NCOLS/4)*NSPLIT)     // 102400 threads in kernel 2
#define NBLK2 (NTH2/TPB2)           // 400 blocks

// SSIM constants in raw-sum space (multiplied through by 1331^4)
#define C1S 1.0559354e-3f           // 0.01/4096^2 * 1331^2
#define C2S 3.1678061e-3f           // 0.03/4096^2 * 1331^2
#define EPSS 31384.2838f            // 1e-8 * 1331^4

// Global scratch: pair-interleaved half2 fields.
// g_pair[0][v] = half2(Sx, Sy) ; g_pair[1][v] = half2(Sq, Sxy)
__device__ __align__(16) unsigned int g_pair[2][TOTAL];
__device__ float g_l1p[NBLK1];
__device__ float g_ssimp[NBLK2];

__device__ __forceinline__ unsigned int pack2(float a, float b)
{
    __half2 h = __floats2half2_rn(a, b);
    return *reinterpret_cast<unsigned int*>(&h);
}
__device__ __forceinline__ float2 unpack2(unsigned int u)
{
    __half2 h = *reinterpret_cast<__half2*>(&u);
    return __half22float2(h);
}

// ---------------------------------------------------------------------------
// Kernel 1: per (b,d,h-tile): products + sliding W-sum + sliding H-sum.
// float2-interleaved slab, half2-packed product planes, uint2 global stores.
// ---------------------------------------------------------------------------
__global__ void __launch_bounds__(256, 3) wh_kernel(const float* __restrict__ x,
                                                    const float* __restrict__ y)
{
    extern __shared__ float sm[];
    float2* slab = (float2*)sm;                         // HR*SF2 float2
    unsigned int* sp = (unsigned int*)(sm + 2*HR*SF2);  // 2 planes * HR * SPU
    __shared__ float red[256];

    const int tid = threadIdx.x;
    const int th  = blockIdx.x;             // 0..NTILE-1
    const int d   = blockIdx.y;             // 0..159
    const int b   = blockIdx.z;             // 0..1
    const int h0  = th * TH;
    const size_t base = ((size_t)b*DD + d) * SLICE;

    // ---- Stage 1: vectorized halo'd slab load + fused smooth-L1 on owned rows
    float l1acc = 0.f;
    const int W4 = WW/4;                    // 40
    for (int idx = tid; idx < HR*W4; idx += 256) {
        int r  = idx / W4;
        int w4 = idx - r*W4;
        int gh = h0 - RAD + r;
        float4 xv = make_float4(0.f,0.f,0.f,0.f);
        float4 yv = make_float4(0.f,0.f,0.f,0.f);
        if (gh >= 0 && gh < HH) {
            size_t g = (base + (size_t)gh*WW + w4*4) >> 2;
            xv = ((const float4*)x)[g];
            yv = ((const float4*)y)[g];
        }
        float2* row = slab + r*SF2 + w4*4;
        row[0] = make_float2(xv.x, yv.x);
        row[1] = make_float2(xv.y, yv.y);
        row[2] = make_float2(xv.z, yv.z);
        row[3] = make_float2(xv.w, yv.w);
        if (r >= RAD && r < RAD + TH) {
            float d0=fabsf(xv.x-yv.x), d1=fabsf(xv.y-yv.y);
            float d2=fabsf(xv.z-yv.z), d3=fabsf(xv.w-yv.w);
            l1acc += (d0<1.f)?0.5f*d0*d0:(d0-0.5f);
            l1acc += (d1<1.f)?0.5f*d1*d1:(d1-0.5f);
            l1acc += (d2<1.f)?0.5f*d2*d2:(d2-0.5f);
            l1acc += (d3<1.f)?0.5f*d3*d3:(d3-0.5f);
        }
    }
    __syncthreads();

    // ---- Stage 2: sliding W-sum, register ring, half2-packed STS
    if (tid < NSEG*HR) {
        int s = tid / HR;               // w-segment
        int r = tid - s*HR;             // row 0..HR-1
        int w0 = s * SEGW;
        const float2* row = slab + r*SF2;
        float2 ring[WIN];
        float a0=0.f, a1=0.f, a2=0.f, a3=0.f;
        #pragma unroll
        for (int i = 0; i < WIN; i++) {
            int t = w0 - RAD + i;
            float2 v = make_float2(0.f, 0.f);
            if (t >= 0) v = row[t];            // t < WW always
            ring[i] = v;
            a0 += v.x; a1 += v.y; a2 += v.x*v.x + v.y*v.y; a3 += v.x*v.y;
        }
        unsigned int* q0 = sp + r*SPU;
        unsigned int* q1 = sp + HR*SPU + r*SPU;
        #pragma unroll
        for (int k = 0; k < SEGW; k++) {
            int w = w0 + k;
            q0[w] = pack2(a0, a1);
            q1[w] = pack2(a2, a3);
            float2 o = ring[k%WIN];
            a0 -= o.x; a1 -= o.y; a2 -= o.x*o.x + o.y*o.y; a3 -= o.x*o.y;
            int tin = w + RAD + 1;
            float2 v = make_float2(0.f, 0.f);
            if (tin < WW) v = row[tin];
            ring[k%WIN] = v;
            a0 += v.x; a1 += v.y; a2 += v.x*v.x + v.y*v.y; a3 += v.x*v.y;
        }
    }
    __syncthreads();

    // ---- Stage 3: sliding H-sum; job = (plane, pair of adjacent w)
    if (tid < 2*(WW/2)) {               // 160 jobs
        int fp = tid / (WW/2);          // plane 0..1
        int w2 = tid - fp*(WW/2);       // 0..79
        const unsigned int* colb = sp + fp*(HR*SPU) + 2*w2;
        float4 ring[WIN];
        float a0=0.f, a1=0.f, a2=0.f, a3=0.f;
        #pragma unroll
        for (int i = 0; i < WIN; i++) {
            float2 pa = unpack2(colb[i*SPU]);
            float2 pb = unpack2(colb[i*SPU + 1]);
            ring[i] = make_float4(pa.x, pa.y, pb.x, pb.y);
            a0 += pa.x; a1 += pa.y; a2 += pb.x; a3 += pb.y;
        }
        unsigned int* gout = g_pair[fp] + base + (size_t)h0*WW + 2*w2;
        #pragma unroll
        for (int ro = 0; ro < TH; ro++) {
            uint2 o;
            o.x = pack2(a0, a1);
            o.y = pack2(a2, a3);
            *reinterpret_cast<uint2*>(gout + (size_t)ro*WW) = o;
            if (ro < TH - 1) {
                float2 pa = unpack2(colb[(ro + WIN)*SPU]);
                float2 pb = unpack2(colb[(ro + WIN)*SPU + 1]);
                float4 og = ring[ro%WIN];
                a0 += pa.x - og.x; a1 += pa.y - og.y;
                a2 += pb.x - og.z; a3 += pb.y - og.w;
                ring[ro%WIN] = make_float4(pa.x, pa.y, pb.x, pb.y);
            }
        }
    }

    // ---- L1 block reduce
    red[tid] = l1acc;
    __syncthreads();
    for (int s2 = 128; s2 > 0; s2 >>= 1) {
        if (tid < s2) red[tid] += red[tid + s2];
        __syncthreads();
    }
    if (tid == 0) {
        int bid = blockIdx.x + NTILE*(blockIdx.y + DD*blockIdx.z);
        g_l1p[bid] = red[0];
    }
}

// ---------------------------------------------------------------------------
// Kernel 2: sliding D-sum over 4 columns/thread via 2 uint4 loads per step.
// ---------------------------------------------------------------------------
__device__ __forceinline__ float ssim_elem(float Sx, float Sy, float Sq, float Sxy)
{
    float q  = 2.f * Sx * Sy;
    float T  = Sx*Sx + Sy*Sy;
    float N1 = q + C1S;
    float N2 = fmaf(2662.f, Sxy, C2S - q);
    float D1 = T + C1S;
    float D2 = fmaf(1331.f, Sq, C2S - T);
    float ss = __fdividef(N1*N2, fmaf(D1, D2, EPSS));
    float v  = 0.5f - 0.5f*ss;
    return fminf(fmaxf(v, 0.f), 1.f);
}

__device__ __forceinline__ void accum(const uint4 p, const uint4 q,
                                      float* Sx, float* Sy, float* Sq, float* Sxy,
                                      float sgn)
{
    float2 v;
    v = unpack2(p.x); Sx[0] += sgn*v.x; Sy[0] += sgn*v.y;
    v = unpack2(p.y); Sx[1] += sgn*v.x; Sy[1] += sgn*v.y;
    v = unpack2(p.z); Sx[2] += sgn*v.x; Sy[2] += sgn*v.y;
    v = unpack2(p.w); Sx[3] += sgn*v.x; Sy[3] += sgn*v.y;
    v = unpack2(q.x); Sq[0] += sgn*v.x; Sxy[0] += sgn*v.y;
    v = unpack2(q.y); Sq[1] += sgn*v.x; Sxy[1] += sgn*v.y;
    v = unpack2(q.z); Sq[2] += sgn*v.x; Sxy[2] += sgn*v.y;
    v = unpack2(q.w); Sq[3] += sgn*v.x; Sxy[3] += sgn*v.y;
}

__global__ void __launch_bounds__(TPB2) dpass_kernel()
{
    const int gid   = blockIdx.x * TPB2 + threadIdx.x;   // 0..NTH2-1
    const int QC    = NCOLS/4;                           // 12800
    const int split = gid / QC;
    const int c4    = gid - split*QC;
    const int col   = c4 * 4;
    const int b     = col / SLICE;
    const int hw    = col - b*SLICE;
    const size_t b4 = ((size_t)b*VOL + hw) >> 2;         // uint4 index
    const int S4 = SLICE/4;                              // 6400

    const uint4* __restrict__ P0 = (const uint4*)g_pair[0] + b4;
    const uint4* __restrict__ P1 = (const uint4*)g_pair[1] + b4;

    float Sx[4]  = {0,0,0,0};
    float Sy[4]  = {0,0,0,0};
    float Sq[4]  = {0,0,0,0};
    float Sxy[4] = {0,0,0,0};

    const int d0 = split * DR;
    int tlo = d0 - RAD; if (tlo < 0) tlo = 0;
    for (int t = tlo; t <= d0 + RAD; t++) {
        size_t o = (size_t)t * S4;
        accum(P0[o], P1[o], Sx, Sy, Sq, Sxy, 1.f);
    }

    float acc = 0.f;
    if (split != 0 && split != NSPLIT-1) {
        // interior: no d-boundary checks -> unconditional loads, unrollable
        #pragma unroll 4
        for (int d = d0; d < d0 + DR; d++) {
            #pragma unroll
            for (int i = 0; i < 4; i++)
                acc += ssim_elem(Sx[i], Sy[i], Sq[i], Sxy[i]);
            size_t oi = (size_t)(d + RAD + 1) * S4;
            size_t oo = (size_t)(d - RAD) * S4;
            accum(P0[oi], P1[oi], Sx, Sy, Sq, Sxy,  1.f);
            accum(P0[oo], P1[oo], Sx, Sy, Sq, Sxy, -1.f);
        }
    } else {
        for (int d = d0; d < d0 + DR; d++) {
            #pragma unroll
            for (int i = 0; i < 4; i++)
                acc += ssim_elem(Sx[i], Sy[i], Sq[i], Sxy[i]);
            if (d < d0 + DR - 1) {
                int tin  = d + RAD + 1;
                int tout = d - RAD;
                if (tin < DD) {
                    size_t o = (size_t)tin * S4;
                    accum(P0[o], P1[o], Sx, Sy, Sq, Sxy, 1.f);
                }
                if (tout >= 0) {
                    size_t o = (size_t)tout * S4;
                    accum(P0[o], P1[o], Sx, Sy, Sq, Sxy, -1.f);
                }
            }
        }
    }

    __shared__ float red[TPB2];
    red[threadIdx.x] = acc;
    __syncthreads();
    for (int s2 = TPB2/2; s2 > 0; s2 >>= 1) {
        if (threadIdx.x < s2) red[threadIdx.x] += red[threadIdx.x + s2];
        __syncthreads();
    }
    if (threadIdx.x == 0) g_ssimp[blockIdx.x] = red[0];
}

// ---------------------------------------------------------------------------
// Kernel 3: finalize in double precision.
// ---------------------------------------------------------------------------
__global__ void finalize_kernel(float* __restrict__ out)
{
    __shared__ double red[256];
    const int tid = threadIdx.x;

    double a = 0.0;
    for (int i = tid; i < NBLK1; i += 256) a += (double)g_l1p[i];
    red[tid] = a; __syncthreads();
    for (int s = 128; s > 0; s >>= 1) {
        if (tid < s) red[tid] += red[tid + s];
        __syncthreads();
    }
    double l1sum = red[0];
    __syncthreads();

    double c = 0.0;
    for (int i = tid; i < NBLK2; i += 256) c += (double)g_ssimp[i];
    red[tid] = c; __syncthreads();
    for (int s = 128; s > 0; s >>= 1) {
        if (tid < s) red[tid] += red[tid + s];
        __syncthreads();
    }
    if (tid == 0) {
        double ssim_mean = red[0] / (double)TOTAL;
        double l1_mean   = l1sum  / (double)TOTAL;
        out[0] = (float)(0.85 * ssim_mean + 0.15 * l1_mean);
    }
}

// ---------------------------------------------------------------------------
extern "C" void kernel_launch(void* const* d_in, const int* in_sizes, int n_in,
                              void* d_out, int out_size)
{
    const float* pred   = (const float*)d_in[0];
    const float* target = (const float*)d_in[1];
    float* out = (float*)d_out;

    // dynamic smem: float2 slab + 2 half2 product planes
    const int smem_bytes = HR*SF2*(int)sizeof(float2) + 2*HR*SPU*(int)sizeof(unsigned int); // 66,976 B
    cudaFuncSetAttribute(wh_kernel, cudaFuncAttributeMaxDynamicSharedMemorySize, smem_bytes);

    dim3 g1(NTILE, DD, BB);   // 3200 blocks
    wh_kernel<<<g1, 256, smem_bytes>>>(pred, target);
    dpass_kernel<<<NBLK2, TPB2>>>();
    finalize_kernel<<<1, 256>>>(out);
}